// round 12
// baseline (speedup 1.0000x reference)
#include <cuda_runtime.h>
#include <math.h>

#define BB 16
#define NN 2048   // samp points (rows)
#define MM 8192   // ref points (cols)

// Scratch: partial minima (written, never read-modify — no init needed)
__device__ float g_row[4][BB][NN];     // per m-quarter: min d2 for each samp point
__device__ float g_col[16][BB][MM];    // per n-slab:    min d2 for each ref point
__device__ float g_part[BB][9][2];     // stage-1 partial sums

typedef unsigned long long ull;

__device__ __forceinline__ ull pack2(float v) {
    ull r;
    asm("mov.b64 %0, {%1, %1};" : "=l"(r) : "f"(v));
    return r;
}
__device__ __forceinline__ ull pack_ab(float a, float b) {
    ull r;
    asm("mov.b64 %0, {%1, %2};" : "=l"(r) : "f"(a), "f"(b));
    return r;
}
__device__ __forceinline__ ull ffma2(ull a, ull b, ull c) {
    ull d;
    asm("fma.rn.f32x2 %0, %1, %2, %3;" : "=l"(d) : "l"(a), "l"(b), "l"(c));
    return d;
}
__device__ __forceinline__ ull add2(ull a, ull b) {
    ull d;
    asm("add.rn.f32x2 %0, %1, %2;" : "=l"(d) : "l"(a), "l"(b));
    return d;
}
__device__ __forceinline__ float2 unpack2(ull v) {
    float2 f;
    asm("mov.b64 {%0, %1}, %2;" : "=f"(f.x), "=f"(f.y) : "l"(v));
    return f;
}

// Fused kernel: block covers 128 samp rows x 2048 ref cols.
// Each lane owns 8 ref cols in registers as 4 f32x2 pairs; packed FMA chain,
// scalar FMNMX mins. NO warp-collective ops in the mainloop: per row each
// lane stores its 8-col partial min via fire-and-forget STS; a cheap per-chunk
// reduction pass (every 32 rows) folds 256 lane-partials per row and writes
// g_row directly.
// grid = (mq=4, slab=16, b=16), block = 256 (8 warps), 4 blocks/SM.
__global__ void __launch_bounds__(256, 4) chamfer_fused(const float* __restrict__ samp,
                                                        const float* __restrict__ ref) {
    __shared__ float4 stage[512];          // ref staging chunk (reused 4x)
    __shared__ ulonglong4 rowsP[128];      // samp rows packed dup
    __shared__ float rowpart[8][33][33];   // per-lane row partials for one 32-row chunk
                                           // [warp][row-in-chunk][lane]; padded dims
                                           // decorrelate banks for the read pass

    const int mq   = blockIdx.x;
    const int slab = blockIdx.y;
    const int b    = blockIdx.z;
    const int tid  = threadIdx.x;
    const int w    = tid >> 5;
    const int l    = tid & 31;

    const float* refb  = ref  + ((size_t)b * MM + mq * 2048) * 3;
    const float* sampb = samp + ((size_t)b * NN + slab * 128) * 3;

    // ---- load samp rows (prescaled, packed-duplicated) ----
    if (tid < 128) {
        float x = sampb[tid * 3 + 0];
        float y = sampb[tid * 3 + 1];
        float z = sampb[tid * 3 + 2];
        ulonglong4 r;
        r.x = pack2(-2.f * x);
        r.y = pack2(-2.f * y);
        r.z = pack2(-2.f * z);
        r.w = pack2(x * x + y * y + z * z);
        rowsP[tid] = r;
    }

    // ---- stage ref cols in 4 chunks of 512; pick up 8 cols as 4 packed pairs ----
    ull cxp[4], cyp[4], czp[4], cwp[4];
    for (int c = 0; c < 4; c++) {
        __syncthreads();
        for (int i = tid; i < 512; i += 256) {
            const float* p = refb + (c * 512 + i) * 3;
            float x = p[0], y = p[1], z = p[2];
            stage[i] = make_float4(x, y, z, x * x + y * y + z * z);
        }
        __syncthreads();
        if ((w >> 1) == c) {
            const int base = (w & 1) * 256 + l;
#pragma unroll
            for (int k = 0; k < 4; k++) {
                float4 a = stage[base + (2 * k) * 32];
                float4 d = stage[base + (2 * k + 1) * 32];
                cxp[k] = pack_ab(a.x, d.x);
                cyp[k] = pack_ab(a.y, d.y);
                czp[k] = pack_ab(a.z, d.z);
                cwp[k] = pack_ab(a.w, d.w);
            }
        }
    }
    __syncthreads();

    float colacc[8];
#pragma unroll
    for (int j = 0; j < 8; j++) colacc[j] = INFINITY;

    const int rr = tid >> 3;   // phase-B: row in chunk (0..31)
    const int jj = tid & 7;    // phase-B: warp-slot (0..7)

    // ---- mainloop in 4 chunks of 32 rows; zero warp-collectives inside ----
    for (int c = 0; c < 4; c++) {
#pragma unroll
        for (int i = 0; i < 32; i++) {
            const int r = c * 32 + i;
            const ulonglong4 q = rowsP[r];
            float pm[4];
#pragma unroll
            for (int k = 0; k < 4; k++) {
                ull t = ffma2(q.z, czp[k], cwp[k]);
                t = ffma2(q.y, cyp[k], t);
                t = ffma2(q.x, cxp[k], t);
                ull d = add2(t, q.w);                 // full packed d2 pair
                float2 df = unpack2(d);
                colacc[2 * k]     = fminf(colacc[2 * k], df.x);
                colacc[2 * k + 1] = fminf(colacc[2 * k + 1], df.y);
                pm[k] = fminf(df.x, df.y);
            }
            rowpart[w][i][l] = fminf(fminf(pm[0], pm[1]), fminf(pm[2], pm[3]));
        }
        __syncthreads();   // drains STS; rowpart complete for this chunk

        // phase B: 8 threads per row scan 32 lane-partials each, fold via shfl
        {
            float m = rowpart[jj][rr][0];
#pragma unroll
            for (int k = 1; k < 32; k++) m = fminf(m, rowpart[jj][rr][k]);
            m = fminf(m, __shfl_down_sync(0xffffffffu, m, 4));
            m = fminf(m, __shfl_down_sync(0xffffffffu, m, 2));
            m = fminf(m, __shfl_down_sync(0xffffffffu, m, 1));
            if (jj == 0)
                g_row[mq][b][slab * 128 + c * 32 + rr] = fmaxf(m, 0.f);
        }
        __syncthreads();   // protect rowpart before next chunk overwrites
    }

    // ---- emit col partials (complete over this block's 128 rows) ----
    {
        const int mbase = mq * 2048 + w * 256 + l;
#pragma unroll
        for (int j = 0; j < 8; j++)
            g_col[slab][b][mbase + j * 32] = fmaxf(colacc[j], 0.f);
    }
}

// Stage 1: combine partials, sqrt, partial sums. grid=(piece=9, b=16).
__global__ void __launch_bounds__(256) final1_kernel() {
    const int piece = blockIdx.x, b = blockIdx.y, tid = threadIdx.x;
    float sd = 0.f, ss = 0.f;
    if (piece == 0) {
        for (int n = tid; n < NN; n += 256) {
            float v = fminf(fminf(g_row[0][b][n], g_row[1][b][n]),
                            fminf(g_row[2][b][n], g_row[3][b][n]));
            sd += v;
            ss += sqrtf(v);
        }
    } else {
        const int m0 = (piece - 1) * 1024;
        for (int m = m0 + tid; m < m0 + 1024; m += 256) {
            float v = g_col[0][b][m];
#pragma unroll
            for (int s = 1; s < 16; s++) v = fminf(v, g_col[s][b][m]);
            sd += v;
            ss += sqrtf(v);
        }
    }
    __shared__ float sh[2][256];
    sh[0][tid] = sd;
    sh[1][tid] = ss;
    __syncthreads();
    for (int s = 128; s > 0; s >>= 1) {
        if (tid < s) {
            sh[0][tid] += sh[0][tid + s];
            sh[1][tid] += sh[1][tid + s];
        }
        __syncthreads();
    }
    if (tid == 0) {
        g_part[b][piece][0] = sh[0][0];
        g_part[b][piece][1] = sh[1][0];
    }
}

__global__ void final2_kernel(float* __restrict__ out) {
    const int b = blockIdx.x;
    if (threadIdx.x == 0) {
        float rowd = g_part[b][0][0], rows = g_part[b][0][1];
        float cold = 0.f, cols = 0.f;
#pragma unroll
        for (int p = 1; p < 9; p++) {
            cold += g_part[b][p][0];
            cols += g_part[b][p][1];
        }
        float meanA = rowd / (float)NN;
        float meanAs = rows / (float)NN;
        float meanB = cold / (float)MM;
        float meanBs = cols / (float)MM;
        out[b] = 0.5f * (meanAs + meanBs);  // cd_p
        out[16 + b] = meanA + meanB;        // cd_t
    }
}

extern "C" void kernel_launch(void* const* d_in, const int* in_sizes, int n_in,
                              void* d_out, int out_size) {
    const float* ref;
    const float* samp;
    if (in_sizes[0] == BB * MM * 3) {
        ref = (const float*)d_in[0];
        samp = (const float*)d_in[1];
    } else {
        ref = (const float*)d_in[1];
        samp = (const float*)d_in[0];
    }
    float* out = (float*)d_out;

    chamfer_fused<<<dim3(4, 16, 16), 256>>>(samp, ref);
    final1_kernel<<<dim3(9, BB), 256>>>();
    final2_kernel<<<BB, 32>>>(out);
}

// round 13
// speedup vs baseline: 1.1816x; 1.1816x over previous
#include <cuda_runtime.h>
#include <math.h>

#define BB 16
#define NN 2048   // samp points (rows)
#define MM 8192   // ref points (cols)

// Scratch: partial minima (written, never read-modify — no init needed)
// NOTE: values are UNCLAMPED (can be tiny-negative); final1 clamps.
__device__ float g_row[4][BB][NN];     // per m-quarter: min d2 for each samp point
__device__ float g_col[16][BB][MM];    // per n-slab:    min d2 for each ref point
__device__ float g_part[BB][9][2];     // stage-1 partial sums

typedef unsigned long long ull;

__device__ __forceinline__ ull pack2(float v) {
    ull r;
    asm("mov.b64 %0, {%1, %1};" : "=l"(r) : "f"(v));
    return r;
}
__device__ __forceinline__ ull pack_ab(float a, float b) {
    ull r;
    asm("mov.b64 %0, {%1, %2};" : "=l"(r) : "f"(a), "f"(b));
    return r;
}
__device__ __forceinline__ ull ffma2(ull a, ull b, ull c) {
    ull d;
    asm("fma.rn.f32x2 %0, %1, %2, %3;" : "=l"(d) : "l"(a), "l"(b), "l"(c));
    return d;
}
__device__ __forceinline__ ull add2(ull a, ull b) {
    ull d;
    asm("add.rn.f32x2 %0, %1, %2;" : "=l"(d) : "l"(a), "l"(b));
    return d;
}
__device__ __forceinline__ float2 unpack2(ull v) {
    float2 f;
    asm("mov.b64 {%0, %1}, %2;" : "=f"(f.x), "=f"(f.y) : "l"(v));
    return f;
}

// Fused kernel: block covers 128 samp rows x 2048 ref cols.
// Each lane owns 8 ref cols in registers as 4 f32x2 pairs; packed FMA chain,
// scalar FMNMX mins, one redux.sync.min.s32 per row (signed-int order on float
// bits: exact for non-negatives; any negative result is clamped downstream,
// matching clamp(true min)). No clamps in the hot loop.
// grid = (mq=4, slab=16, b=16), block = 256 (8 warps), 4 blocks/SM.
__global__ void __launch_bounds__(256, 4) chamfer_fused(const float* __restrict__ samp,
                                                        const float* __restrict__ ref) {
    __shared__ float4 stage[512];        // ref staging chunk (reused 4x)
    __shared__ ulonglong4 rowsP[128];    // samp rows packed dup
    __shared__ float rowred[8][128];     // per-warp row minima (UNCLAMPED)

    const int mq   = blockIdx.x;
    const int slab = blockIdx.y;
    const int b    = blockIdx.z;
    const int tid  = threadIdx.x;
    const int w    = tid >> 5;
    const int l    = tid & 31;

    const float* refb  = ref  + ((size_t)b * MM + mq * 2048) * 3;
    const float* sampb = samp + ((size_t)b * NN + slab * 128) * 3;

    // ---- load samp rows (prescaled, packed-duplicated) ----
    if (tid < 128) {
        float x = sampb[tid * 3 + 0];
        float y = sampb[tid * 3 + 1];
        float z = sampb[tid * 3 + 2];
        ulonglong4 r;
        r.x = pack2(-2.f * x);
        r.y = pack2(-2.f * y);
        r.z = pack2(-2.f * z);
        r.w = pack2(x * x + y * y + z * z);
        rowsP[tid] = r;
    }

    // ---- stage ref cols in 4 chunks of 512; pick up 8 cols as 4 packed pairs ----
    ull cxp[4], cyp[4], czp[4], cwp[4];
    for (int c = 0; c < 4; c++) {
        __syncthreads();
        for (int i = tid; i < 512; i += 256) {
            const float* p = refb + (c * 512 + i) * 3;
            float x = p[0], y = p[1], z = p[2];
            stage[i] = make_float4(x, y, z, x * x + y * y + z * z);
        }
        __syncthreads();
        if ((w >> 1) == c) {
            const int base = (w & 1) * 256 + l;
#pragma unroll
            for (int k = 0; k < 4; k++) {
                float4 a = stage[base + (2 * k) * 32];
                float4 d = stage[base + (2 * k + 1) * 32];
                cxp[k] = pack_ab(a.x, d.x);
                cyp[k] = pack_ab(a.y, d.y);
                czp[k] = pack_ab(a.z, d.z);
                cwp[k] = pack_ab(a.w, d.w);
            }
        }
    }
    __syncthreads();

    float colacc[8];
#pragma unroll
    for (int j = 0; j < 8; j++) colacc[j] = INFINITY;

    // ---- mainloop: packed FMA chain; 1 signed-int REDUX per row; no clamps ----
#pragma unroll 32
    for (int r = 0; r < 128; r++) {
        const ulonglong4 q = rowsP[r];
        float pm[4];
#pragma unroll
        for (int k = 0; k < 4; k++) {
            ull t = ffma2(q.z, czp[k], cwp[k]);
            t = ffma2(q.y, cyp[k], t);
            t = ffma2(q.x, cxp[k], t);
            ull d = add2(t, q.w);                 // full packed d2 pair
            float2 df = unpack2(d);
            colacc[2 * k]     = fminf(colacc[2 * k], df.x);
            colacc[2 * k + 1] = fminf(colacc[2 * k + 1], df.y);
            pm[k] = fminf(df.x, df.y);
        }
        float rp = fminf(fminf(pm[0], pm[1]), fminf(pm[2], pm[3]));
        // signed-int min == float min for non-negatives; any negative result
        // is clamped in final1, identical to clamp(true min).
        int rm = __reduce_min_sync(0xffffffffu, __float_as_int(rp));
        if (l == 0) rowred[w][r] = __int_as_float(rm);
    }

    // ---- emit col partials (complete within block over its 128 rows) ----
    {
        const int mbase = mq * 2048 + w * 256 + l;
#pragma unroll
        for (int j = 0; j < 8; j++)
            g_col[slab][b][mbase + j * 32] = colacc[j];   // unclamped
    }

    // ---- combine row partials across the 8 warps ----
    __syncthreads();
    if (tid < 128) {
        float v = rowred[0][tid];
#pragma unroll
        for (int k = 1; k < 8; k++) v = fminf(v, rowred[k][tid]);
        g_row[mq][b][slab * 128 + tid] = v;   // unclamped
    }
}

// Stage 1: combine partials, CLAMP, sqrt, partial sums. grid=(piece=9, b=16).
__global__ void __launch_bounds__(256) final1_kernel() {
    const int piece = blockIdx.x, b = blockIdx.y, tid = threadIdx.x;
    float sd = 0.f, ss = 0.f;
    if (piece == 0) {
        for (int n = tid; n < NN; n += 256) {
            float v = fminf(fminf(g_row[0][b][n], g_row[1][b][n]),
                            fminf(g_row[2][b][n], g_row[3][b][n]));
            v = fmaxf(v, 0.f);
            sd += v;
            ss += sqrtf(v);
        }
    } else {
        const int m0 = (piece - 1) * 1024;
        for (int m = m0 + tid; m < m0 + 1024; m += 256) {
            float v = g_col[0][b][m];
#pragma unroll
            for (int s = 1; s < 16; s++) v = fminf(v, g_col[s][b][m]);
            v = fmaxf(v, 0.f);
            sd += v;
            ss += sqrtf(v);
        }
    }
    __shared__ float sh[2][256];
    sh[0][tid] = sd;
    sh[1][tid] = ss;
    __syncthreads();
    for (int s = 128; s > 0; s >>= 1) {
        if (tid < s) {
            sh[0][tid] += sh[0][tid + s];
            sh[1][tid] += sh[1][tid + s];
        }
        __syncthreads();
    }
    if (tid == 0) {
        g_part[b][piece][0] = sh[0][0];
        g_part[b][piece][1] = sh[1][0];
    }
}

__global__ void final2_kernel(float* __restrict__ out) {
    const int b = blockIdx.x;
    if (threadIdx.x == 0) {
        float rowd = g_part[b][0][0], rows = g_part[b][0][1];
        float cold = 0.f, cols = 0.f;
#pragma unroll
        for (int p = 1; p < 9; p++) {
            cold += g_part[b][p][0];
            cols += g_part[b][p][1];
        }
        float meanA = rowd / (float)NN;
        float meanAs = rows / (float)NN;
        float meanB = cold / (float)MM;
        float meanBs = cols / (float)MM;
        out[b] = 0.5f * (meanAs + meanBs);  // cd_p
        out[16 + b] = meanA + meanB;        // cd_t
    }
}

extern "C" void kernel_launch(void* const* d_in, const int* in_sizes, int n_in,
                              void* d_out, int out_size) {
    const float* ref;
    const float* samp;
    if (in_sizes[0] == BB * MM * 3) {
        ref = (const float*)d_in[0];
        samp = (const float*)d_in[1];
    } else {
        ref = (const float*)d_in[1];
        samp = (const float*)d_in[0];
    }
    float* out = (float*)d_out;

    chamfer_fused<<<dim3(4, 16, 16), 256>>>(samp, ref);
    final1_kernel<<<dim3(9, BB), 256>>>();
    final2_kernel<<<BB, 32>>>(out);
}